// round 8
// baseline (speedup 1.0000x reference)
#include <cuda_runtime.h>
#include <cuda_fp16.h>
#include <cstdint>
#include <cstddef>

// Problem constants: B=4, S=4096 -> N=16384 tokens
#define N_TOK 16384
#define DIM   4096
#define OUT_D 4096
#define SCALING 0.5f
#define W1_N8 18   // 144 rows / 8: 16 A-blocks + router-hi + router-lo

// -------- static scratch, fp16 fragment-major (m16n8k16) --------
// GEMM1 B operand: [k16 0..255][n8 0..17][lane*2 + reg]  (reg=(k>>3)&1)
__device__ __align__(16) uint32_t g_w1f[256 * W1_N8 * 64];
// GEMM2 B operand: [n8 0..511][k16 0..7][lane*2 + reg]
__device__ __align__(16) uint32_t g_btf[512 * 8 * 64];
// GEMM2 A operand: [m16 0..1023][k16 0..7][lane*4 + reg]
__device__ __align__(16) uint32_t g_hwf[(size_t)1024 * 8 * 128];

// -------- helpers --------
__device__ __forceinline__ uint32_t pack_f16x2(float lo, float hi) {
    uint32_t r;   // d.low = 2nd src, d.high = 1st src
    asm("cvt.rn.f16x2.f32 %0, %1, %2;" : "=r"(r) : "f"(hi), "f"(lo));
    return r;
}
__device__ __forceinline__ float2 unpack_f16x2(uint32_t v) {
    __half2 h = *(__half2*)&v;
    return __half22float2(h);
}
__device__ __forceinline__ void mma_f16(float* c, const uint32_t* a,
                                        uint32_t b0, uint32_t b1) {
    asm volatile(
        "mma.sync.aligned.m16n8k16.row.col.f32.f16.f16.f32 "
        "{%0,%1,%2,%3}, {%4,%5,%6,%7}, {%8,%9}, {%0,%1,%2,%3};\n"
        : "+f"(c[0]), "+f"(c[1]), "+f"(c[2]), "+f"(c[3])
        : "r"(a[0]), "r"(a[1]), "r"(a[2]), "r"(a[3]), "r"(b0), "r"(b1));
}
__device__ __forceinline__ void cp16(void* dst, const void* src) {
    uint32_t d = (uint32_t)__cvta_generic_to_shared(dst);
    asm volatile("cp.async.cg.shared.global [%0], [%1], 16;" :: "r"(d), "l"(src));
}
#define CP_COMMIT() asm volatile("cp.async.commit_group;")
#define CP_WAIT(n)  asm volatile("cp.async.wait_group %0;" :: "n"(n))

// ============================================================================
// Prep: build fp16 fragment-major operand tensors once.
// B-frag map (col-major n8 x k16): lane=(n&7)*4+((k&7)>>1), reg=(k>>3)&1, half=k&1
// A-frag map (row-major m16 x k16): lane=(r&7)*4+((c&7)>>1), reg=(r>>3)+2*(c>>3)
// ============================================================================
__global__ void prep_kernel(const float* __restrict__ rw,
                            const float* __restrict__ A,
                            const float* __restrict__ Bm)
{
    const int nthr = gridDim.x * blockDim.x;
    const int tid0 = blockIdx.x * blockDim.x + threadIdx.x;
    // W1: rows 0-127 A, 128-135 router hi, 136-143 router lo residual
    for (int i = tid0; i < 144 * 2048; i += nthr) {
        int n = i >> 11, k = (i & 2047) * 2;
        float v0, v1;
        if (n < 128) {
            v0 = A[n * 4096 + k]; v1 = A[n * 4096 + k + 1];
        } else if (n < 136) {
            v0 = rw[(n - 128) * 4096 + k]; v1 = rw[(n - 128) * 4096 + k + 1];
        } else {
            float f0 = rw[(n - 136) * 4096 + k];
            float f1 = rw[(n - 136) * 4096 + k + 1];
            v0 = f0 - __half2float(__float2half_rn(f0));
            v1 = f1 - __half2float(__float2half_rn(f1));
        }
        int idx = ((k >> 4) * W1_N8 + (n >> 3)) * 64
                + ((n & 7) * 4 + ((k & 7) >> 1)) * 2 + ((k >> 3) & 1);
        g_w1f[idx] = pack_f16x2(v0, v1);
    }
    // Bt: element (o, c): Bm[e][o][r]*SCALING, c = e*16+r
    for (int i = tid0; i < 4096 * 64; i += nthr) {
        int o = i >> 6, c = (i & 63) * 2;
        int e = c >> 4, r = c & 15;
        const float* bp = Bm + ((size_t)e * 4096 + o) * 16 + r;
        int idx = ((o >> 3) * 8 + (c >> 4)) * 64
                + ((o & 7) * 4 + ((c & 7) >> 1)) * 2 + ((c >> 3) & 1);
        g_btf[idx] = pack_f16x2(bp[0] * SCALING, bp[1] * SCALING);
    }
}

// ============================================================================
// GEMM1: C[N,144] = X @ W1^T (fp16 mma, compensated logits), fused gating,
// hw emitted directly in GEMM2 A-fragment order.  (unchanged from R7)
// ============================================================================
#define AS_WORDS (4 * 128 * 32)          // 16384
#define WS_STAGE (2 * W1_N8 * 64)        // 2304
#define WS_WORDS (4 * WS_STAGE)          // 9216
#define SM1_WORDS (AS_WORDS + WS_WORDS + 1024 + 1024)

__global__ __launch_bounds__(256, 1)
void gemm1_kernel(const float* __restrict__ x, const float* __restrict__ rb)
{
    extern __shared__ uint32_t smu[];
    uint32_t* As   = smu;
    uint32_t* Ws   = smu + AS_WORDS;
    float*    gw   = (float*)(smu + AS_WORDS + WS_WORDS);          // [128][8]
    float*    lbuf = (float*)(smu + AS_WORDS + WS_WORDS + 1024);   // [8][32][4]

    const int tid  = threadIdx.x;
    const int lane = tid & 31;
    const int warp = tid >> 5;
    const int wm   = warp & 3;
    const int wn   = warp >> 2;
    const int g    = lane >> 2;
    const int tig  = lane & 3;
    const int m0   = blockIdx.x * 128;
    const int ncol0 = wn * 64;

    float acc[2][9][4];
#pragma unroll
    for (int mt = 0; mt < 2; mt++)
#pragma unroll
        for (int nt = 0; nt < 9; nt++)
#pragma unroll
            for (int i = 0; i < 4; i++) acc[mt][nt][i] = 0.f;

    auto issue = [&](int stage, int t) {
        const int k0 = t * 32;
        uint32_t* ab = As + stage * 128 * 32;
        uint32_t* wb = Ws + stage * WS_STAGE;
#pragma unroll
        for (int i = 0; i < 4; i++) {
            int idx = tid + i * 256, row = idx >> 3, c4 = idx & 7;
            int col = (4 * c4) ^ ((row & 7) * 4);
            cp16(ab + row * 32 + col, x + (size_t)(m0 + row) * DIM + k0 + 4 * c4);
        }
#pragma unroll
        for (int i = 0; i < 3; i++) {
            int idx = tid + i * 256;
            if (idx < 576)
                cp16(wb + idx * 4, g_w1f + (size_t)t * WS_STAGE + idx * 4);
        }
    };

    issue(0, 0); CP_COMMIT();
    issue(1, 1); CP_COMMIT();
    issue(2, 2); CP_COMMIT();

    const int T = DIM / 32;   // 128
    for (int t = 0; t < T; ++t) {
        CP_WAIT(2);
        __syncthreads();
        if (t + 3 < T) issue((t + 3) & 3, t + 3);
        CP_COMMIT();

        const uint32_t* a = As + (t & 3) * 128 * 32;
        const uint32_t* w = Ws + (t & 3) * WS_STAGE;
        const bool do_logits = (wn == (t & 1));
#pragma unroll
        for (int ks = 0; ks < 2; ++ks) {
            const int k = ks * 16;
            uint32_t af[2][4];
            float2 raw[2][4];
#pragma unroll
            for (int mt = 0; mt < 2; ++mt) {
                const int r0 = wm * 32 + mt * 16 + g;
                const int clo = k + 2 * tig, chi = k + 8 + 2 * tig;
                const int alo0 = r0 * 32 + (((clo & ~3) ^ ((r0 & 7) * 4)) | (clo & 3));
                const int alo1 = (r0 + 8) * 32 + (((clo & ~3) ^ (((r0 + 8) & 7) * 4)) | (clo & 3));
                const int ahi0 = r0 * 32 + (((chi & ~3) ^ ((r0 & 7) * 4)) | (chi & 3));
                const int ahi1 = (r0 + 8) * 32 + (((chi & ~3) ^ (((r0 + 8) & 7) * 4)) | (chi & 3));
                raw[mt][0] = *(const float2*)(a + alo0);
                raw[mt][1] = *(const float2*)(a + alo1);
                raw[mt][2] = *(const float2*)(a + ahi0);
                raw[mt][3] = *(const float2*)(a + ahi1);
#pragma unroll
                for (int j = 0; j < 4; j++)
                    af[mt][j] = pack_f16x2(raw[mt][j].x, raw[mt][j].y);
            }
#pragma unroll
            for (int nt = 0; nt < 8; ++nt) {
                const int n8 = wn * 8 + nt;
                uint2 bb = *(const uint2*)(w + (ks * W1_N8 + n8) * 64 + lane * 2);
                mma_f16(acc[0][nt], af[0], bb.x, bb.y);
                mma_f16(acc[1][nt], af[1], bb.x, bb.y);
            }
            if (do_logits) {
                uint32_t alo[2][4];
#pragma unroll
                for (int mt = 0; mt < 2; ++mt)
#pragma unroll
                    for (int j = 0; j < 4; j++) {
                        float2 hv = unpack_f16x2(af[mt][j]);
                        alo[mt][j] = pack_f16x2(raw[mt][j].x - hv.x,
                                                raw[mt][j].y - hv.y);
                    }
                uint2 bh = *(const uint2*)(w + (ks * W1_N8 + 16) * 64 + lane * 2);
                uint2 bl = *(const uint2*)(w + (ks * W1_N8 + 17) * 64 + lane * 2);
                mma_f16(acc[0][8], af[0], bh.x, bh.y);
                mma_f16(acc[1][8], af[1], bh.x, bh.y);
                mma_f16(acc[0][8], af[0], bl.x, bl.y);
                mma_f16(acc[1][8], af[1], bl.x, bl.y);
                mma_f16(acc[0][8], alo[0], bh.x, bh.y);
                mma_f16(acc[1][8], alo[1], bh.x, bh.y);
            }
        }
    }

    if (wn == 0) {
#pragma unroll
        for (int mt = 0; mt < 2; ++mt)
#pragma unroll
            for (int j = 0; j < 4; ++j)
                lbuf[((wm * 2 + mt) * 32 + lane) * 4 + j] = acc[mt][8][j];
    }
    __syncthreads();

    if (wn == 1) {
        const float rb0 = rb[2 * tig];
        const float rb1 = rb[2 * tig + 1];
#pragma unroll
        for (int mt = 0; mt < 2; ++mt) {
#pragma unroll
            for (int j = 0; j < 4; ++j)
                acc[mt][8][j] += lbuf[((wm * 2 + mt) * 32 + lane) * 4 + j];
#pragma unroll
            for (int half = 0; half < 2; ++half) {
                float l0 = acc[mt][8][half * 2 + 0] + rb0;
                float l1 = acc[mt][8][half * 2 + 1] + rb1;
                float m1, m2; int i1, i2;
                if (l0 >= l1) { m1 = l0; i1 = 2 * tig;     m2 = l1; i2 = 2 * tig + 1; }
                else          { m1 = l1; i1 = 2 * tig + 1; m2 = l0; i2 = 2 * tig; }
#pragma unroll
                for (int d = 1; d <= 2; d <<= 1) {
                    float om1 = __shfl_xor_sync(0xffffffffu, m1, d);
                    int   oi1 = __shfl_xor_sync(0xffffffffu, i1, d);
                    float om2 = __shfl_xor_sync(0xffffffffu, m2, d);
                    int   oi2 = __shfl_xor_sync(0xffffffffu, i2, d);
                    if (om1 > m1) {
                        if (m1 >= om2) { m2 = m1; i2 = i1; }
                        else           { m2 = om2; i2 = oi2; }
                        m1 = om1; i1 = oi1;
                    } else if (om1 > m2) { m2 = om1; i2 = oi1; }
                }
                float g1 = 1.f / (1.f + __expf(m2 - m1));
                float g2 = 1.f - g1;
                int row = wm * 32 + mt * 16 + half * 8 + g;
                gw[row * 8 + 2 * tig]     = (2 * tig     == i1) ? g1 : ((2 * tig     == i2) ? g2 : 0.f);
                gw[row * 8 + 2 * tig + 1] = (2 * tig + 1 == i1) ? g1 : ((2 * tig + 1 == i2) ? g2 : 0.f);
            }
        }
    }
    __syncthreads();

#pragma unroll
    for (int mt = 0; mt < 2; ++mt) {
#pragma unroll
        for (int nt = 0; nt < 8; ++nt) {
            const int col = ncol0 + nt * 8 + 2 * tig;
            const int e  = col >> 4;
            const int ra = wm * 32 + mt * 16 + g;
            const float wa = gw[ra * 8 + e];
            const float wb = gw[(ra + 8) * 8 + e];
            uint32_t w0 = pack_f16x2(acc[mt][nt][0] * wa, acc[mt][nt][1] * wa);
            uint32_t w1 = pack_f16x2(acc[mt][nt][2] * wb, acc[mt][nt][3] * wb);
            const int m16 = (m0 + wm * 32 + mt * 16) >> 4;
            const int k16 = wn * 4 + (nt >> 1);
            *(uint2*)(g_hwf + ((size_t)m16 * 8 + k16) * 128
                            + lane * 4 + 2 * (nt & 1)) = make_uint2(w0, w1);
        }
    }
}

// ============================================================================
// GEMM2: out[N,4096] = hw @ Bt^T (fp16 mma).
// Block 128m x 128n, 8 warps of 32x64. B resident (32KB) + A double-buffered
// via cp.async (2x32KB) -> 96KB smem -> 2 CTAs/SM, grid 256 all-resident.
// ============================================================================
#define BS2_WORDS (16 * 8 * 64)             // 8192 (32 KB)
#define AS2_WORDS 8192                      // per stage: 128 rows x 8 k16 x ... 32 KB
#define SM2_WORDS (BS2_WORDS + 2 * AS2_WORDS)   // 24576 words = 96 KB

__global__ __launch_bounds__(256, 2)
void gemm2_kernel(float* __restrict__ out)
{
    extern __shared__ uint32_t smu[];
    uint32_t* Bs = smu;                 // [16 n8][8 k16][64]
    uint32_t* As = smu + BS2_WORDS;     // [2][8 m16][8 k16][128]

    const int tid  = threadIdx.x;
    const int lane = tid & 31;
    const int warp = tid >> 5;
    const int wm   = warp & 3;        // 4 m-groups of 32 rows (2 m16)
    const int wn   = warp >> 2;       // 2 n-groups of 64 cols
    const int nb   = blockIdx.x & 31; // n-block (128 cols)
    const int mc   = blockIdx.x >> 5; // 0..7, 16 m-tiles (128 rows) each

    // ---- B once (group 0) ----
#pragma unroll
    for (int i = 0; i < 8; i++) {
        int idx = tid + i * 256;
        cp16(Bs + idx * 4, g_btf + (size_t)nb * 8192 + idx * 4);
    }
    CP_COMMIT();

    auto issueA = [&](int stage, int it) {
        const size_t src = (size_t)(mc * 16 + it) * 8192;   // m-tile slab
        uint32_t* dst = As + stage * AS2_WORDS;
#pragma unroll
        for (int i = 0; i < 8; i++) {
            int idx = tid + i * 256;
            cp16(dst + idx * 4, g_hwf + src + idx * 4);
        }
    };
    issueA(0, 0); CP_COMMIT();
    issueA(1, 1); CP_COMMIT();
    CP_WAIT(1);            // B + A0 landed
    __syncthreads();

    const int n0 = nb * 128;
    for (int it = 0; it < 16; ++it) {
        const uint32_t* a = As + (it & 1) * AS2_WORDS;

        float acc[2][8][4];
#pragma unroll
        for (int mt = 0; mt < 2; mt++)
#pragma unroll
            for (int nt = 0; nt < 8; nt++)
#pragma unroll
                for (int i = 0; i < 4; i++) acc[mt][nt][i] = 0.f;

#pragma unroll
        for (int ks = 0; ks < 8; ++ks) {
            uint4 af[2];
#pragma unroll
            for (int mt = 0; mt < 2; mt++)
                af[mt] = *(const uint4*)(a + ((wm * 2 + mt) * 8 + ks) * 128 + lane * 4);
            uint2 bf[8];
#pragma unroll
            for (int nt = 0; nt < 8; nt++) {
                const int n8l = wn * 8 + nt;
                bf[nt] = *(const uint2*)(Bs + (n8l * 8 + ks) * 64 + lane * 2);
            }
#pragma unroll
            for (int nt = 0; nt < 8; nt++)
#pragma unroll
                for (int mt = 0; mt < 2; mt++)
                    mma_f16(acc[mt][nt], (const uint32_t*)&af[mt], bf[nt].x, bf[nt].y);
        }

        // ---- store tile it ----
        {
            const int g   = lane >> 2;
            const int tig = lane & 3;
            const int mbase = (mc * 16 + it) * 128;
#pragma unroll
            for (int mt = 0; mt < 2; ++mt) {
#pragma unroll
                for (int nt = 0; nt < 8; ++nt) {
                    const int col = n0 + wn * 64 + nt * 8 + 2 * tig;
                    const int ra  = mbase + wm * 32 + mt * 16 + g;
                    *(float2*)(out + (size_t)ra * OUT_D + col) =
                        make_float2(acc[mt][nt][0], acc[mt][nt][1]);
                    *(float2*)(out + (size_t)(ra + 8) * OUT_D + col) =
                        make_float2(acc[mt][nt][2], acc[mt][nt][3]);
                }
            }
        }

        __syncthreads();                       // all warps done with As[it&1]
        if (it + 2 < 16) issueA(it & 1, it + 2);
        CP_COMMIT();
        CP_WAIT(1);                            // A(it+1) landed
        __syncthreads();
    }
}

// ============================================================================
extern "C" void kernel_launch(void* const* d_in, const int* in_sizes, int n_in,
                              void* d_out, int out_size)
{
    const float* x  = (const float*)d_in[0];   // [N, 4096]
    const float* rw = (const float*)d_in[1];   // [8, 4096]
    const float* rb = (const float*)d_in[2];   // [8]
    const float* A  = (const float*)d_in[3];   // [8,16,4096]
    const float* Bm = (const float*)d_in[4];   // [8,4096,16]
    float* out = (float*)d_out;                // [N, 4096] fp32

    const int sm1 = SM1_WORDS * 4;   // 110592 B
    const int sm2 = SM2_WORDS * 4;   // 98304 B
    cudaFuncSetAttribute(gemm1_kernel,
                         cudaFuncAttributeMaxDynamicSharedMemorySize, sm1);
    cudaFuncSetAttribute(gemm2_kernel,
                         cudaFuncAttributeMaxDynamicSharedMemorySize, sm2);

    prep_kernel<<<1024, 256>>>(rw, A, Bm);
    gemm1_kernel<<<N_TOK / 128, 256, sm1>>>(x, rb);
    gemm2_kernel<<<256, 256, sm2>>>(out);
}